// round 9
// baseline (speedup 1.0000x reference)
#include <cuda_runtime.h>
#include <cstddef>

#define BATCH 16
#define NPB   262144            // 512*512 elements per batch image
#define TAU_F 0.1f
#define SMOOTH_F 0.1f
#define TILE  128
#define NTILES (NPB / TILE)     // 2048
#define GRID_MAIN 296
#define ROWLEN 132              // staged row stride (16B-aligned, conflict-free)
#define BT (BATCH * TILE)       // 2048 floats per array per stage

#define RAW_STAGE_FLOATS (5 * BT)                   // 10240
#define RAW_FLOATS (2 * RAW_STAGE_FLOATS)           // 20480
#define STAGED_FLOATS (BATCH * ROWLEN)              // 2112
#define SMEM_FLOATS (RAW_FLOATS + 2 * STAGED_FLOATS)
#define SMEM_BYTES (SMEM_FLOATS * 4)                // 98816

// Global accumulators. Zero at module load; fused finalize re-zeroes after
// consuming, so every launch/graph replay starts from zero state.
__device__ float g_cross[BATCH * BATCH];
__device__ float g_sq1[BATCH];
__device__ float g_sq2[BATCH];
__device__ float g_pos[BATCH];
__device__ float g_dice[3];
__device__ unsigned int g_done;

__device__ __forceinline__ float sigf(float x) {
    float e = __expf(-x);
    float r;
    asm("rcp.approx.f32 %0, %1;" : "=f"(r) : "f"(1.0f + e));
    return r;
}

__device__ __forceinline__ void fma2(unsigned long long& d,
                                     unsigned long long a,
                                     unsigned long long b) {
    asm("fma.rn.f32x2 %0, %1, %2, %0;" : "+l"(d) : "l"(a), "l"(b));
}
__device__ __forceinline__ float lo_f(unsigned long long v) {
    return __uint_as_float((unsigned int)(v & 0xffffffffu));
}
__device__ __forceinline__ float hi_f(unsigned long long v) {
    return __uint_as_float((unsigned int)(v >> 32));
}

__device__ __forceinline__ void cp16(unsigned int dst, const float* src) {
    asm volatile("cp.async.cg.shared.global [%0], [%1], 16;"
                 :: "r"(dst), "l"(src) : "memory");
}

__global__ void __launch_bounds__(256, 2)
main_kernel(const float* __restrict__ pred, const float* __restrict__ gt,
            const float* __restrict__ in1,  const float* __restrict__ in2,
            const float* __restrict__ msk,
            float* __restrict__ out, int out_size)
{
    extern __shared__ float smem[];
    float* raw   = smem;                          // [2][5][16][128]
    float* s1_sh = smem + RAW_FLOATS;             // [16][ROWLEN]
    float* s2_sh = s1_sh + STAGED_FLOATS;         // [16][ROWLEN]
    __shared__ unsigned int s_islast;

    const int tid  = threadIdx.x;
    const int lane = tid & 31;
    const int w    = tid >> 5;
    const int b    = tid >> 4;     // 0..15
    const int j    = tid & 15;     // 0..15

    // gmem pointers offset to this thread's (batch, float4 slot)
    const size_t boff = (size_t)b * NPB + (size_t)(4 * j);
    const float* p_in1  = in1  + boff;
    const float* p_in2  = in2  + boff;
    const float* p_msk  = msk  + boff;
    const float* p_pred = pred + boff;
    const float* p_gt   = gt   + boff;

    // smem dst base for this thread's cp.asyncs (bytes, shared window)
    const unsigned int raw_u32 =
        (unsigned int)__cvta_generic_to_shared(raw) +
        (unsigned int)((b * TILE + 4 * j) * 4);

    // Phase B mapping: warp w owns a disjoint 4x8 block of the 16x16 Gram.
    const int b1b = (w & 3) * 4;
    const int b2b = (w >> 2) * 8;
    const int tb  = lane * 4;

    unsigned long long c2[4][8];
#pragma unroll
    for (int i = 0; i < 4; i++)
#pragma unroll
        for (int jj = 0; jj < 8; jj++) c2[i][jj] = 0ull;

    float sq1a = 0.0f, sq2a = 0.0f, posa = 0.0f;
    float dP = 0.0f, dG = 0.0f, dPG = 0.0f;

    // ---- fetch stage: 10 cp.async (5 arrays x 2 segments), always commit ----
    auto fetch = [&](int tk, int buf) {
        if (tk < NTILES) {
            const size_t base = (size_t)tk * TILE;
            const unsigned int d0 = raw_u32 +
                (unsigned int)(buf * RAW_STAGE_FLOATS * 4);
#pragma unroll
            for (int s = 0; s < 2; s++) {
                const unsigned int ds = d0 + (unsigned int)(s * 64 * 4);
                const size_t gs = base + (size_t)(s * 64);
                cp16(ds + 0 * BT * 4, p_in1  + gs);
                cp16(ds + 1 * BT * 4, p_in2  + gs);
                cp16(ds + 2 * BT * 4, p_msk  + gs);
                cp16(ds + 3 * BT * 4, p_pred + gs);
                cp16(ds + 4 * BT * 4, p_gt   + gs);
            }
        }
        asm volatile("cp.async.commit_group;");
    };

    // Prologue: every block has >= 2 tiles (min 6)
    fetch(blockIdx.x,             0);
    fetch(blockIdx.x + GRID_MAIN, 1);

    int k = 0;
    for (int tk = blockIdx.x; tk < NTILES; tk += GRID_MAIN, k++) {
        const int buf = k & 1;
        asm volatile("cp.async.wait_group 1;");   // oldest group (this stage) done
        __syncthreads();                          // stage visible + prior Phase B done

        // ---- Phase A: read raw from smem, sigmoid, stage, pointwise accum ----
        const float* rb = raw + buf * RAW_STAGE_FLOATS + b * TILE + 4 * j;
#pragma unroll
        for (int s = 0; s < 2; s++) {
            const int t = s * 64 + 4 * j;
            const float4 x1 = *(const float4*)(rb + 0 * BT + s * 64);
            const float4 x2 = *(const float4*)(rb + 1 * BT + s * 64);
            const float4 mm = *(const float4*)(rb + 2 * BT + s * 64);
            const float4 pp = *(const float4*)(rb + 3 * BT + s * 64);
            const float4 gg = *(const float4*)(rb + 4 * BT + s * 64);

            float4 s1v, s2v;
            s1v.x = sigf(x1.x); s1v.y = sigf(x1.y); s1v.z = sigf(x1.z); s1v.w = sigf(x1.w);
            s2v.x = sigf(x2.x); s2v.y = sigf(x2.y); s2v.z = sigf(x2.z); s2v.w = sigf(x2.w);
            *(float4*)&s1_sh[b * ROWLEN + t] = s1v;
            *(float4*)&s2_sh[b * ROWLEN + t] = s2v;

            const float s1a[4] = {s1v.x, s1v.y, s1v.z, s1v.w};
            const float s2a[4] = {s2v.x, s2v.y, s2v.z, s2v.w};
            const float mv[4]  = {mm.x, mm.y, mm.z, mm.w};
            const float pv[4]  = {pp.x, pp.y, pp.z, pp.w};
            const float gv[4]  = {gg.x, gg.y, gg.z, gg.w};

#pragma unroll
            for (int kk = 0; kk < 4; kk++) {
                const float d = mv[kk] * (s1a[kk] - s2a[kk]);
                posa = fmaf(d, d, posa);
                sq1a = fmaf(s1a[kk], s1a[kk], sq1a);
                sq2a = fmaf(s2a[kk], s2a[kk], sq2a);
                const float sp = sigf(pv[kk]);
                dP  += sp;
                dG  += gv[kk];
                dPG = fmaf(sp, gv[kk], dPG);
            }
        }
        __syncthreads();           // staged ready; raw[buf] fully consumed

        // Refill this buffer for tile k+2 (overlaps Phase B + next Phase A)
        fetch(tk + 2 * GRID_MAIN, buf);

        // ---- Phase B: 4x8 Gram block via packed f32x2 FMA ----
        ulonglong2 av[4];
#pragma unroll
        for (int i = 0; i < 4; i++)
            av[i] = *(const ulonglong2*)&s1_sh[(b1b + i) * ROWLEN + tb];
#pragma unroll
        for (int jj = 0; jj < 8; jj++) {
            const ulonglong2 bv = *(const ulonglong2*)&s2_sh[(b2b + jj) * ROWLEN + tb];
#pragma unroll
            for (int i = 0; i < 4; i++) {
                fma2(c2[i][jj], av[i].x, bv.x);
                fma2(c2[i][jj], av[i].y, bv.y);
            }
        }
    }

    // ---- Reductions (all shuffles full-warp, unconditional) ----
#pragma unroll
    for (int i = 0; i < 4; i++) {
#pragma unroll
        for (int jj = 0; jj < 8; jj++) {
            float v = lo_f(c2[i][jj]) + hi_f(c2[i][jj]);
            v += __shfl_xor_sync(0xffffffffu, v, 16);
            v += __shfl_xor_sync(0xffffffffu, v, 8);
            v += __shfl_xor_sync(0xffffffffu, v, 4);
            v += __shfl_xor_sync(0xffffffffu, v, 2);
            v += __shfl_xor_sync(0xffffffffu, v, 1);
            if (lane == 0) atomicAdd(&g_cross[(b1b + i) * BATCH + (b2b + jj)], v);
        }
    }

#pragma unroll
    for (int off = 8; off >= 1; off >>= 1) {
        posa += __shfl_xor_sync(0xffffffffu, posa, off);
        sq1a += __shfl_xor_sync(0xffffffffu, sq1a, off);
        sq2a += __shfl_xor_sync(0xffffffffu, sq2a, off);
    }
    if ((lane & 15) == 0) {
        atomicAdd(&g_pos[b], posa);
        atomicAdd(&g_sq1[b], sq1a);
        atomicAdd(&g_sq2[b], sq2a);
    }

#pragma unroll
    for (int off = 16; off >= 1; off >>= 1) {
        dP  += __shfl_xor_sync(0xffffffffu, dP,  off);
        dG  += __shfl_xor_sync(0xffffffffu, dG,  off);
        dPG += __shfl_xor_sync(0xffffffffu, dPG, off);
    }
    if (lane == 0) {
        atomicAdd(&g_dice[0], dP);
        atomicAdd(&g_dice[1], dG);
        atomicAdd(&g_dice[2], dPG);
    }

    // ---- Last-block fused finalize ----
    __threadfence();
    if (tid == 0)
        s_islast = (atomicAdd(&g_done, 1u) == (unsigned)(GRID_MAIN - 1));
    __syncthreads();
    if (!s_islast) return;

    {
        float* s_simneg = s1_sh;           // reuse staged smem
        float* s_loss   = s1_sh + BATCH;
        float* s_dice   = s1_sh + 2 * BATCH;

        const int b1 = tid >> 4;
        const int b2 = tid & 15;
        const float invN = 1.0f / (float)NPB;

        const float r_cross = __ldcg(&g_cross[tid]);
        const float r_sq1   = __ldcg(&g_sq1[b1]);
        const float r_sq2   = __ldcg(&g_sq2[b2]);
        const float r_pos   = (tid < BATCH) ? __ldcg(&g_pos[tid]) : 0.0f;
        if (tid < 3) s_dice[tid] = __ldcg(&g_dice[tid]);
        __syncthreads();

        // Re-zero for next replay
        g_cross[tid] = 0.0f;
        if (tid < BATCH) { g_pos[tid] = 0.0f; g_sq1[tid] = 0.0f; g_sq2[tid] = 0.0f; }
        if (tid < 3) g_dice[tid] = 0.0f;
        if (tid == 0) g_done = 0u;

        const float mse = (r_sq1 + r_sq2 - 2.0f * r_cross) * invN;
        float sim = expf(-mse / TAU_F);
        if (b1 == b2) sim = 0.0f;
#pragma unroll
        for (int off = 8; off >= 1; off >>= 1)
            sim += __shfl_xor_sync(0xffffffffu, sim, off);  // all 256 threads execute
        if (b2 == 0) s_simneg[b1] = sim;
        __syncthreads();

        if (tid < BATCH) {
            const float simpos = expf(-(r_pos * invN) / TAU_F);
            s_loss[tid] = -logf(simpos / (simpos + s_simneg[tid]));
        }
        __syncthreads();

        if (tid == 0) {
            float l = 0.0f;
#pragma unroll
            for (int i = 0; i < BATCH; i++) l += s_loss[i];
            const float contrast = l * (1.0f / (float)BATCH);
            const float dice = 1.0f - (2.0f * s_dice[2] + SMOOTH_F) /
                                      (s_dice[0] + s_dice[1] + SMOOTH_F);
            out[0] = dice + contrast;
            if (out_size > 1) out[1] = dice;
            if (out_size > 2) out[2] = 0.0f;
            if (out_size > 3) out[3] = contrast;
        }
    }
}

extern "C" void kernel_launch(void* const* d_in, const int* in_sizes, int n_in,
                              void* d_out, int out_size) {
    const float* pred = (const float*)d_in[0];
    const float* gt   = (const float*)d_in[1];
    const float* in1  = (const float*)d_in[2];
    const float* in2  = (const float*)d_in[3];
    const float* msk  = (const float*)d_in[4];
    float* out = (float*)d_out;

    cudaFuncSetAttribute(main_kernel,
                         cudaFuncAttributeMaxDynamicSharedMemorySize, SMEM_BYTES);
    main_kernel<<<GRID_MAIN, 256, SMEM_BYTES>>>(pred, gt, in1, in2, msk, out, out_size);
}

// round 12
// speedup vs baseline: 1.3953x; 1.3953x over previous
#include <cuda_runtime.h>
#include <cstddef>

#define BATCH 16
#define NPB   262144                  // 512*512 elements per batch image
#define TAU_F 0.1f
#define SMOOTH_F 0.1f
#define THREADS 512
#define C_BLOCKS 176                  // contrastive blocks
#define D_BLOCKS 120                  // dice streaming blocks
#define GRID_ALL (C_BLOCKS + D_BLOCKS)   // 296 = 2 per SM
#define TILE 256
#define NTILES (NPB / TILE)           // 1024
#define ROWLEN 260                    // 256 + 4 pad; 1040B rows (16B-aligned)
#define NV4 ((BATCH * NPB) / 4)       // 1048576 float4 granules

// Global accumulators. Zero at module load; fused finalize re-zeroes after
// consuming, so every launch/graph replay starts from zero state.
__device__ float g_cross[BATCH * BATCH];
__device__ float g_sq1[BATCH];
__device__ float g_sq2[BATCH];
__device__ float g_pos[BATCH];
__device__ float g_dice[3];
__device__ unsigned int g_done;

__device__ __forceinline__ float sigf(float x) {
    float e = __expf(-x);
    float r;
    asm("rcp.approx.f32 %0, %1;" : "=f"(r) : "f"(1.0f + e));
    return r;
}

__global__ void __launch_bounds__(THREADS, 2)
main_kernel(const float* __restrict__ pred, const float* __restrict__ gt,
            const float* __restrict__ in1,  const float* __restrict__ in2,
            const float* __restrict__ msk,
            float* __restrict__ out, int out_size)
{
    __shared__ float s1_sh[BATCH * ROWLEN];
    __shared__ float s2_sh[BATCH * ROWLEN];
    __shared__ unsigned int s_islast;

    const int tid  = threadIdx.x;
    const int lane = tid & 31;
    const int w    = tid >> 5;          // warp id 0..15

    if ((int)blockIdx.x < C_BLOCKS) {
        // ================== CONTRASTIVE PATH ==================
        const int b = w;                // warp w owns batch b in Phase A
        const size_t boff = (size_t)b * NPB + (size_t)(lane * 4);
        const float* p1 = in1 + boff;
        const float* p2 = in2 + boff;
        const float* pm = msk + boff;

        // Phase B: warp w owns a 2x8 Gram block
        const int b1b = (w & 7) * 2;
        const int b2b = (w >> 3) * 8;

        float c[2][8];
#pragma unroll
        for (int i = 0; i < 2; i++)
#pragma unroll
            for (int jj = 0; jj < 8; jj++) c[i][jj] = 0.0f;

        float sq1a = 0.0f, sq2a = 0.0f, posa = 0.0f;

        for (int tk = blockIdx.x; tk < NTILES; tk += C_BLOCKS) {
            const size_t base = (size_t)tk * TILE;
            __syncthreads();   // protect smem from prior Phase B readers

            // ---- Phase A: 6 front-batched LDG.128, sigmoid, stage, accum ----
            const float4 x1a = *(const float4*)(p1 + base);
            const float4 x1b = *(const float4*)(p1 + base + 128);
            const float4 x2a = *(const float4*)(p2 + base);
            const float4 x2b = *(const float4*)(p2 + base + 128);
            const float4 mma = *(const float4*)(pm + base);
            const float4 mmb = *(const float4*)(pm + base + 128);

            float4 s1A, s1B, s2A, s2B;
            s1A.x = sigf(x1a.x); s1A.y = sigf(x1a.y); s1A.z = sigf(x1a.z); s1A.w = sigf(x1a.w);
            s1B.x = sigf(x1b.x); s1B.y = sigf(x1b.y); s1B.z = sigf(x1b.z); s1B.w = sigf(x1b.w);
            s2A.x = sigf(x2a.x); s2A.y = sigf(x2a.y); s2A.z = sigf(x2a.z); s2A.w = sigf(x2a.w);
            s2B.x = sigf(x2b.x); s2B.y = sigf(x2b.y); s2B.z = sigf(x2b.z); s2B.w = sigf(x2b.w);

            *(float4*)&s1_sh[b * ROWLEN + lane * 4]       = s1A;
            *(float4*)&s1_sh[b * ROWLEN + lane * 4 + 128] = s1B;
            *(float4*)&s2_sh[b * ROWLEN + lane * 4]       = s2A;
            *(float4*)&s2_sh[b * ROWLEN + lane * 4 + 128] = s2B;

            {
                const float s1v[8] = {s1A.x,s1A.y,s1A.z,s1A.w, s1B.x,s1B.y,s1B.z,s1B.w};
                const float s2v[8] = {s2A.x,s2A.y,s2A.z,s2A.w, s2B.x,s2B.y,s2B.z,s2B.w};
                const float mv[8]  = {mma.x,mma.y,mma.z,mma.w, mmb.x,mmb.y,mmb.z,mmb.w};
#pragma unroll
                for (int k = 0; k < 8; k++) {
                    const float d = mv[k] * (s1v[k] - s2v[k]);
                    posa = fmaf(d, d, posa);
                    sq1a = fmaf(s1v[k], s1v[k], sq1a);
                    sq2a = fmaf(s2v[k], s2v[k], sq2a);
                }
            }
            __syncthreads();

            // ---- Phase B: 2x8 Gram block; K=256 in two conflict-free halves ----
#pragma unroll
            for (int h = 0; h < 2; h++) {
                const int cb = lane * 4 + h * 128;
                const float4 a0 = *(const float4*)&s1_sh[(b1b + 0) * ROWLEN + cb];
                const float4 a1 = *(const float4*)&s1_sh[(b1b + 1) * ROWLEN + cb];
#pragma unroll
                for (int jj = 0; jj < 8; jj++) {
                    const float4 bv = *(const float4*)&s2_sh[(b2b + jj) * ROWLEN + cb];
                    c[0][jj] = fmaf(a0.x, bv.x, c[0][jj]);
                    c[0][jj] = fmaf(a0.y, bv.y, c[0][jj]);
                    c[0][jj] = fmaf(a0.z, bv.z, c[0][jj]);
                    c[0][jj] = fmaf(a0.w, bv.w, c[0][jj]);
                    c[1][jj] = fmaf(a1.x, bv.x, c[1][jj]);
                    c[1][jj] = fmaf(a1.y, bv.y, c[1][jj]);
                    c[1][jj] = fmaf(a1.z, bv.z, c[1][jj]);
                    c[1][jj] = fmaf(a1.w, bv.w, c[1][jj]);
                }
            }
        }

        // ---- Reductions (full-warp shuffles, unconditional) ----
#pragma unroll
        for (int i = 0; i < 2; i++) {
#pragma unroll
            for (int jj = 0; jj < 8; jj++) {
                float v = c[i][jj];
                v += __shfl_xor_sync(0xffffffffu, v, 16);
                v += __shfl_xor_sync(0xffffffffu, v, 8);
                v += __shfl_xor_sync(0xffffffffu, v, 4);
                v += __shfl_xor_sync(0xffffffffu, v, 2);
                v += __shfl_xor_sync(0xffffffffu, v, 1);
                if (lane == 0) atomicAdd(&g_cross[(b1b + i) * BATCH + (b2b + jj)], v);
            }
        }
#pragma unroll
        for (int off = 16; off >= 1; off >>= 1) {
            posa += __shfl_xor_sync(0xffffffffu, posa, off);
            sq1a += __shfl_xor_sync(0xffffffffu, sq1a, off);
            sq2a += __shfl_xor_sync(0xffffffffu, sq2a, off);
        }
        if (lane == 0) {
            atomicAdd(&g_pos[b], posa);
            atomicAdd(&g_sq1[b], sq1a);
            atomicAdd(&g_sq2[b], sq2a);
        }
    } else {
        // ================== DICE STREAMING PATH (no barriers) ==================
        const float4* pred4 = (const float4*)pred;
        const float4* gt4   = (const float4*)gt;
        float dP = 0.0f, dG = 0.0f, dPG = 0.0f;

        const int gid    = ((int)blockIdx.x - C_BLOCKS) * THREADS + tid;
        const int stride = D_BLOCKS * THREADS;
#pragma unroll 4
        for (int i = gid; i < NV4; i += stride) {
            const float4 pp = pred4[i];
            const float4 gg = gt4[i];
            const float sv[4] = {sigf(pp.x), sigf(pp.y), sigf(pp.z), sigf(pp.w)};
            const float gv[4] = {gg.x, gg.y, gg.z, gg.w};
#pragma unroll
            for (int k = 0; k < 4; k++) {
                dP  += sv[k];
                dG  += gv[k];
                dPG = fmaf(sv[k], gv[k], dPG);
            }
        }
#pragma unroll
        for (int off = 16; off >= 1; off >>= 1) {
            dP  += __shfl_xor_sync(0xffffffffu, dP,  off);
            dG  += __shfl_xor_sync(0xffffffffu, dG,  off);
            dPG += __shfl_xor_sync(0xffffffffu, dPG, off);
        }
        if (lane == 0) {
            atomicAdd(&g_dice[0], dP);
            atomicAdd(&g_dice[1], dG);
            atomicAdd(&g_dice[2], dPG);
        }
    }

    // ---- Last-block fused finalize ----
    __threadfence();
    if (tid == 0)
        s_islast = (atomicAdd(&g_done, 1u) == (unsigned)(GRID_ALL - 1));
    __syncthreads();
    if (!s_islast) return;

    {
        float* s_simneg = s1_sh;           // reuse staged smem
        float* s_loss   = s1_sh + BATCH;
        float* s_dice   = s1_sh + 2 * BATCH;

        const int b1 = tid >> 4;
        const int b2 = tid & 15;
        const float invN = 1.0f / (float)NPB;

        float sim = 0.0f;
        float r_pos = 0.0f;
        if (tid < 256) {                   // warps 0-7 fully active: shuffles safe
            const float r_cross = __ldcg(&g_cross[tid]);
            const float r_sq1   = __ldcg(&g_sq1[b1]);
            const float r_sq2   = __ldcg(&g_sq2[b2]);
            if (tid < BATCH) r_pos = __ldcg(&g_pos[tid]);
            if (tid < 3) s_dice[tid] = __ldcg(&g_dice[tid]);

            const float mse = (r_sq1 + r_sq2 - 2.0f * r_cross) * invN;
            sim = expf(-mse / TAU_F);
            if (b1 == b2) sim = 0.0f;
#pragma unroll
            for (int off = 8; off >= 1; off >>= 1)
                sim += __shfl_xor_sync(0xffffffffu, sim, off);
        }
        __syncthreads();
        if (tid < 256 && b2 == 0) s_simneg[b1] = sim;

        // Re-zero state for next graph replay
        if (tid < 256) g_cross[tid] = 0.0f;
        if (tid < BATCH) { g_pos[tid] = 0.0f; g_sq1[tid] = 0.0f; g_sq2[tid] = 0.0f; }
        if (tid < 3) g_dice[tid] = 0.0f;
        if (tid == 0) g_done = 0u;
        __syncthreads();

        if (tid < BATCH) {
            const float simpos = expf(-(r_pos * invN) / TAU_F);
            s_loss[tid] = -logf(simpos / (simpos + s_simneg[tid]));
        }
        __syncthreads();

        if (tid == 0) {
            float l = 0.0f;
#pragma unroll
            for (int i = 0; i < BATCH; i++) l += s_loss[i];
            const float contrast = l * (1.0f / (float)BATCH);
            const float dice = 1.0f - (2.0f * s_dice[2] + SMOOTH_F) /
                                      (s_dice[0] + s_dice[1] + SMOOTH_F);
            out[0] = dice + contrast;
            if (out_size > 1) out[1] = dice;
            if (out_size > 2) out[2] = 0.0f;
            if (out_size > 3) out[3] = contrast;
        }
    }
}

extern "C" void kernel_launch(void* const* d_in, const int* in_sizes, int n_in,
                              void* d_out, int out_size) {
    const float* pred = (const float*)d_in[0];
    const float* gt   = (const float*)d_in[1];
    const float* in1  = (const float*)d_in[2];
    const float* in2  = (const float*)d_in[3];
    const float* msk  = (const float*)d_in[4];
    float* out = (float*)d_out;

    main_kernel<<<GRID_ALL, THREADS>>>(pred, gt, in1, in2, msk, out, out_size);
}